// round 5
// baseline (speedup 1.0000x reference)
#include <cuda_runtime.h>

#define HH   4
#define FF   32
#define HFD  128          // H*F
#define FIN  128
#define EDIM 64
#define HID  256
#define BB   64
#define MLE  1500
#define NN   (BB*MLE)     // 96000
#define EE   600000
#define CAP  64           // per-node incidence capacity (P(overflow) ~ 1e-50)
#define NBLK 148          // sort passes: one wave

typedef unsigned long long u64;

// ---------------- scratch (device globals; no allocation allowed) ----------
__device__ float g_proj[NN*HFD];      // 49.2 MB
__device__ float g_ss[NN*HH];
__device__ float g_st[NN*HH];
__device__ float g_s[EE*HH];          // scores, then exp(scores - M) in place
__device__ float g_dt[NN*HH];         // softmax denominators (trg branch)
__device__ float g_ds[NN*HH];         // softmax denominators (src branch)
__device__ float g_usrc[BB*HFD];
__device__ float g_utrg[BB*HFD];
__device__ float g_v[BB*HH*EDIM];
__device__ unsigned g_max_ord;
__device__ int g_degt[NN];
__device__ int g_degs[NN];
__device__ int g_listt[NN*CAP];       // edge ids whose trg == n
__device__ int g_lists[NN*CAP];       // edge ids whose src == n
__device__ int g_bh[BB*NBLK];         // per-block batch histograms / offsets
__device__ int g_pe[EE];              // batch-sorted: (b<<24) | edge id

// ---------------- helpers --------------------------------------------------
__device__ __forceinline__ unsigned f2ord(float f) {
    unsigned b = __float_as_uint(f);
    return (b & 0x80000000u) ? ~b : (b | 0x80000000u);
}
__device__ __forceinline__ float ord2f(unsigned u) {
    unsigned b = (u & 0x80000000u) ? (u & 0x7fffffffu) : ~u;
    return __uint_as_float(b);
}
__device__ __forceinline__ void red4(float* addr, float4 v) {
    asm volatile("red.global.add.v4.f32 [%0], {%1,%2,%3,%4};"
                 :: "l"(addr), "f"(v.x), "f"(v.y), "f"(v.z), "f"(v.w) : "memory");
}
__device__ __forceinline__ float lrelu(float x) { return x > 0.f ? x : 0.2f * x; }
__device__ __forceinline__ float comp4(float4 v, int h) {
    return h == 0 ? v.x : h == 1 ? v.y : h == 2 ? v.z : v.w;
}
__device__ __forceinline__ float shfl_comp(float4 v, int src, int h) {
    float e0 = __shfl_sync(0xffffffffu, v.x, src);
    float e1 = __shfl_sync(0xffffffffu, v.y, src);
    float e2 = __shfl_sync(0xffffffffu, v.z, src);
    float e3 = __shfl_sync(0xffffffffu, v.w, src);
    return h == 0 ? e0 : (h == 1 ? e1 : (h == 2 ? e2 : e3));
}
// packed f32x2 (sm_103a FFMA2 — only reachable via PTX)
__device__ __forceinline__ u64 pack2(float lo, float hi) {
    u64 r; asm("mov.b64 %0, {%1, %2};" : "=l"(r) : "f"(lo), "f"(hi)); return r;
}
__device__ __forceinline__ void unpack2(u64 v, float& lo, float& hi) {
    asm("mov.b64 {%0, %1}, %2;" : "=f"(lo), "=f"(hi) : "l"(v));
}
__device__ __forceinline__ u64 fma2(u64 a, u64 b, u64 c) {
    u64 d; asm("fma.rn.f32x2 %0, %1, %2, %3;" : "=l"(d) : "l"(a), "l"(b), "l"(c)); return d;
}

// ---------------- K0: zero counters/denoms + init max ----------------------
__global__ void zero_kernel() {
    int i = blockIdx.x * 256 + threadIdx.x;
    if (i < NN) {
        g_degt[i] = 0; g_degs[i] = 0;
        ((float4*)g_dt)[i] = make_float4(0.f, 0.f, 0.f, 0.f);
        ((float4*)g_ds)[i] = make_float4(0.f, 0.f, 0.f, 0.f);
    }
    if (i == 0) g_max_ord = 0x007FFFFFu;   // encodes -inf
}

// ---------------- sort pass 1: per-block batch histograms ------------------
__global__ void count_kernel(const int* __restrict__ bids) {
    __shared__ int h[BB];
    if (threadIdx.x < BB) h[threadIdx.x] = 0;
    __syncthreads();
    for (int e = blockIdx.x * 256 + threadIdx.x; e < EE; e += NBLK * 256)
        atomicAdd(&h[bids[e]], 1);
    __syncthreads();
    if (threadIdx.x < BB) g_bh[threadIdx.x * NBLK + blockIdx.x] = h[threadIdx.x];
}

// ---------------- sort pass 2: scan (all counters staged in smem) ----------
__global__ void scan_kernel() {
    __shared__ int sh[BB * NBLK];
    __shared__ int tot[BB];
    int t = threadIdx.x;
    for (int i = t; i < BB * NBLK; i += 256) sh[i] = g_bh[i];
    __syncthreads();
    if (t < BB) {
        int run = 0;
        for (int blk = 0; blk < NBLK; blk++) {
            int c = sh[t * NBLK + blk];
            sh[t * NBLK + blk] = run;
            run += c;
        }
        tot[t] = run;
    }
    __syncthreads();
    if (t < BB) {
        int base = 0;
        for (int k = 0; k < t; k++) base += tot[k];
        for (int blk = 0; blk < NBLK; blk++)
            g_bh[t * NBLK + blk] = sh[t * NBLK + blk] + base;
    }
}

// ---------------- sort pass 3: scatter permutation only --------------------
__global__ void scatter_kernel(const int* __restrict__ bids) {
    __shared__ int cur[BB];
    if (threadIdx.x < BB) cur[threadIdx.x] = g_bh[threadIdx.x * NBLK + blockIdx.x];
    __syncthreads();
    for (int e = blockIdx.x * 256 + threadIdx.x; e < EE; e += NBLK * 256) {
        int b = bids[e];
        int pos = atomicAdd(&cur[b], 1);
        g_pe[pos] = (b << 24) | e;
    }
}

// ---------------- K1: per-batch instruction bridges ------------------------
__global__ void prep_kernel(const float* __restrict__ ins,
                            const float* __restrict__ Wsi, const float* __restrict__ bsi,
                            const float* __restrict__ Wti, const float* __restrict__ bti,
                            const float* __restrict__ Wei, const float* __restrict__ bei,
                            const float* __restrict__ asrc, const float* __restrict__ atrg,
                            const float* __restrict__ aedge, const float* __restrict__ Wedge) {
    __shared__ float si[HID];
    __shared__ float ce[HFD];
    int b = blockIdx.x, t = threadIdx.x;   // 128 threads
    for (int k = t; k < HID; k += 128) si[k] = ins[b * HID + k];
    __syncthreads();
    float s1 = bsi[t], s2 = bti[t], s3 = bei[t];
    for (int k = 0; k < HID; k++) {
        float iv = si[k];
        s1 += iv * Wsi[k * HFD + t];
        s2 += iv * Wti[k * HFD + t];
        s3 += iv * Wei[k * HFD + t];
    }
    g_usrc[b * HFD + t] = s1 * asrc[t];
    g_utrg[b * HFD + t] = s2 * atrg[t];
    ce[t] = s3 * aedge[t];
    __syncthreads();
    for (int o = t; o < HH * EDIM; o += 128) {
        int h = o >> 6, d = o & 63;
        float v = 0.f;
        #pragma unroll
        for (int f = 0; f < FF; f++) v += Wedge[d * HFD + h * FF + f] * ce[h * FF + f];
        g_v[b * HH * EDIM + o] = v;
    }
}

// ---------------- K2: fused node GEMM (FFMA2) + scores + skip init ---------
#define TILE_N 64
#define KCOLS  256
#define SMEM_BYTES ((FIN*KCOLS + TILE_N*129) * 4)

__global__ void node_kernel(const float* __restrict__ x,
                            const float* __restrict__ Wp,
                            const float* __restrict__ Wsk,
                            const float* __restrict__ bias,
                            float* __restrict__ out) {
    extern __shared__ float smem[];
    float* sW = smem;                 // [128][256]
    float* sX = smem + FIN * KCOLS;   // [64][129] padded (reused as proj tile)
    int tid = threadIdx.x;

    const float4* Wp4 = (const float4*)Wp;
    const float4* Ws4 = (const float4*)Wsk;
    for (int i4 = tid; i4 < FIN * KCOLS / 4; i4 += 256) {
        int k = i4 >> 6, c4 = i4 & 63;
        float4 v = (c4 < 32) ? Wp4[k * 32 + c4] : Ws4[k * 32 + (c4 - 32)];
        ((float4*)sW)[i4] = v;
    }
    int base = blockIdx.x * TILE_N;
    const float4* x4 = (const float4*)x;
    for (int i = tid; i < TILE_N * 32; i += 256) {
        int r = i >> 5, k4 = i & 31;
        float4 v = x4[(base + r) * 32 + k4];
        int s = r * 129 + k4 * 4;
        sX[s] = v.x; sX[s + 1] = v.y; sX[s + 2] = v.z; sX[s + 3] = v.w;
    }
    __syncthreads();

    int tcol = tid & 31, trow = tid >> 5;
    u64 acc2[8][4];
    #pragma unroll
    for (int j = 0; j < 8; j++)
        #pragma unroll
        for (int i = 0; i < 4; i++) acc2[j][i] = 0ull;

    for (int k = 0; k < FIN; k++) {
        u64 xr2[8], wr2[4];
        #pragma unroll
        for (int j = 0; j < 8; j++) {
            float xv = sX[(trow * 8 + j) * 129 + k];        // broadcast
            xr2[j] = pack2(xv, xv);
        }
        #pragma unroll
        for (int i = 0; i < 4; i++)
            wr2[i] = *(const u64*)&sW[k * KCOLS + 2 * (tcol + 32 * i)];
        #pragma unroll
        for (int j = 0; j < 8; j++)
            #pragma unroll
            for (int i = 0; i < 4; i++) acc2[j][i] = fma2(xr2[j], wr2[i], acc2[j][i]);
    }
    __syncthreads();

    #pragma unroll
    for (int j = 0; j < 8; j++) {
        int ln = trow * 8 + j;
        int gn = base + ln;
        #pragma unroll
        for (int i = 0; i < 4; i++) {
            int c0 = 2 * (tcol + 32 * i);
            float lo, hi; unpack2(acc2[j][i], lo, hi);
            if (i < 2) {
                *(float2*)&g_proj[gn * HFD + c0] = make_float2(lo, hi);
                sX[ln * 129 + c0] = lo;
                sX[ln * 129 + c0 + 1] = hi;
            } else {
                int oj = c0 - HFD;
                float o0 = lo + bias[oj];
                float o1 = hi + bias[oj + 1];
                out[(size_t)gn * 256 + oj] = o0;
                out[(size_t)gn * 256 + oj + 1] = o1;
                out[(size_t)gn * 256 + 128 + oj] = o0;
                out[(size_t)gn * 256 + 128 + oj + 1] = o1;
            }
        }
    }
    __syncthreads();

    int ln = tid & 63, h = tid >> 6;
    int gn = base + ln;
    int b = gn / MLE;
    const float* us = g_usrc + b * HFD + h * FF;
    const float* ut = g_utrg + b * HFD + h * FF;
    const float* pr = sX + ln * 129 + h * FF;
    float a = 0.f, c2 = 0.f;
    #pragma unroll
    for (int f = 0; f < FF; f++) { float p = pr[f]; a = fmaf(p, us[f], a); c2 = fmaf(p, ut[f], c2); }
    g_ss[gn * HH + h] = a;
    g_st[gn * HH + h] = c2;
}

// ---------------- K3: per-edge scores (batch-sorted walk) + lists ----------
// warp-uniform b -> all v loads are LDS broadcasts (4-phase floor)
#define SV_F4 (BB*65)
#define ESC_SMEM (SV_F4*16)

__global__ void escore_kernel(const int* __restrict__ eidx,
                              const float* __restrict__ edges) {
    extern __shared__ float4 sv[];
    const float4* v4 = (const float4*)g_v;
    for (int i = threadIdx.x; i < BB * 64; i += 256) {
        int b = i >> 6, r = i & 63;
        sv[b * 65 + r] = v4[i];
    }
    __syncthreads();

    float m = -3.4e38f;
    for (int i = blockIdx.x * 256 + threadIdx.x; i < EE; i += gridDim.x * 256) {
        int w = g_pe[i];
        int e = w & 0xFFFFFF;
        int b = w >> 24;
        int src = __ldg(eidx + e), trg = __ldg(eidx + EE + e);
        const float4* er = (const float4*)edges + e * 16;
        const float4* vb = sv + b * 65;      // uniform within warp -> broadcast
        float se0 = 0.f, se1 = 0.f, se2 = 0.f, se3 = 0.f;
        #pragma unroll
        for (int q = 0; q < 16; q++) {
            float4 ev = er[q];
            float4 v0 = vb[q], v1 = vb[16 + q], v2 = vb[32 + q], v3 = vb[48 + q];
            se0 += ev.x * v0.x + ev.y * v0.y + ev.z * v0.z + ev.w * v0.w;
            se1 += ev.x * v1.x + ev.y * v1.y + ev.z * v1.z + ev.w * v1.w;
            se2 += ev.x * v2.x + ev.y * v2.y + ev.z * v2.z + ev.w * v2.w;
            se3 += ev.x * v3.x + ev.y * v3.y + ev.z * v3.z + ev.w * v3.w;
        }
        float4 ss = ((const float4*)g_ss)[src];
        float4 st = ((const float4*)g_st)[trg];
        float s0 = lrelu(ss.x + st.x + se0);
        float s1 = lrelu(ss.y + st.y + se1);
        float s2 = lrelu(ss.z + st.z + se2);
        float s3 = lrelu(ss.w + st.w + se3);
        ((float4*)g_s)[e] = make_float4(s0, s1, s2, s3);   // original layout
        m = fmaxf(m, fmaxf(fmaxf(s0, s1), fmaxf(s2, s3)));
        // incidence lists (LTS atomics overlap the L1-bound dot product)
        int pt = atomicAdd(&g_degt[trg], 1);
        if (pt < CAP) g_listt[trg * CAP + pt] = e;
        int ps = atomicAdd(&g_degs[src], 1);
        if (ps < CAP) g_lists[src * CAP + ps] = e;
    }
    #pragma unroll
    for (int off = 16; off; off >>= 1) m = fmaxf(m, __shfl_xor_sync(0xffffffffu, m, off));
    __shared__ float wm[8];
    if ((threadIdx.x & 31) == 0) wm[threadIdx.x >> 5] = m;
    __syncthreads();
    if (threadIdx.x < 8) {
        m = wm[threadIdx.x];
        #pragma unroll
        for (int off = 4; off; off >>= 1) m = fmaxf(m, __shfl_xor_sync(0xffu, m, off));
        if (threadIdx.x == 0) atomicMax(&g_max_ord, f2ord(m));
    }
}

// ---------------- K4: exp in place + denominators (pure stream) ------------
__global__ void fill_kernel(const int* __restrict__ eidx) {
    int e = blockIdx.x * 256 + threadIdx.x;
    if (e >= EE) return;
    float M = ord2f(g_max_ord);
    float4 s = ((const float4*)g_s)[e];
    float4 ex = make_float4(__expf(s.x - M), __expf(s.y - M),
                            __expf(s.z - M), __expf(s.w - M));
    ((float4*)g_s)[e] = ex;
    int src = eidx[e], trg = eidx[EE + e];
    red4(g_dt + trg * 4, ex);
    red4(g_ds + src * 4, ex);
}

// ---------------- K5: gather aggregation + skip + LayerNorm ----------------
__global__ void gather_kernel(const int* __restrict__ eidx,
                              const float* __restrict__ gamma,
                              const float* __restrict__ beta,
                              float* __restrict__ out) {
    int n = blockIdx.x * 8 + (threadIdx.x >> 5);
    int lane = threadIdx.x & 31;
    int h = lane >> 3;
    int dt = g_degt[n]; if (dt > CAP) dt = CAP;
    int ds = g_degs[n]; if (ds > CAP) ds = CAP;
    const float4* ex4 = (const float4*)g_s;
    const float4* pr4 = (const float4*)g_proj;

    float rT = 1.f / (comp4(((const float4*)g_dt)[n], h) + 1e-16f);
    float rS = 1.f / (comp4(((const float4*)g_ds)[n], h) + 1e-16f);

    float4 aT = make_float4(0.f, 0.f, 0.f, 0.f);
    float4 aS = make_float4(0.f, 0.f, 0.f, 0.f);

    // ---- trg-aggregated branch (neighbors = src endpoints) ----
    {
        int m32 = dt < 32 ? dt : 32;
        int nbr_l = 0; float4 ex_l = make_float4(0.f, 0.f, 0.f, 0.f);
        if (lane < m32) {
            int e = g_listt[n * CAP + lane];
            nbr_l = __ldg(eidx + e);
            ex_l = __ldg(ex4 + e);
        }
        for (int it = 0; it < m32; it += 4) {
            #pragma unroll
            for (int j = 0; j < 4; j++) {
                int idx = it + j;
                int nbr = __shfl_sync(0xffffffffu, nbr_l, idx & 31);
                float a = shfl_comp(ex_l, idx & 31, h);
                if (idx < m32) {
                    float4 p = __ldg(pr4 + nbr * 32 + lane);
                    aT.x += p.x * a; aT.y += p.y * a; aT.z += p.z * a; aT.w += p.w * a;
                }
            }
        }
        for (int it = 32; it < dt; it++) {
            int e = g_listt[n * CAP + it];
            float a = comp4(ex4[e], h);
            int nbr = eidx[e];
            float4 p = pr4[nbr * 32 + lane];
            aT.x += p.x * a; aT.y += p.y * a; aT.z += p.z * a; aT.w += p.w * a;
        }
    }
    // ---- src-aggregated branch (neighbors = trg endpoints) ----
    {
        int m32 = ds < 32 ? ds : 32;
        int nbr_l = 0; float4 ex_l = make_float4(0.f, 0.f, 0.f, 0.f);
        if (lane < m32) {
            int e = g_lists[n * CAP + lane];
            nbr_l = __ldg(eidx + EE + e);
            ex_l = __ldg(ex4 + e);
        }
        for (int it = 0; it < m32; it += 4) {
            #pragma unroll
            for (int j = 0; j < 4; j++) {
                int idx = it + j;
                int nbr = __shfl_sync(0xffffffffu, nbr_l, idx & 31);
                float a = shfl_comp(ex_l, idx & 31, h);
                if (idx < m32) {
                    float4 p = __ldg(pr4 + nbr * 32 + lane);
                    aS.x += p.x * a; aS.y += p.y * a; aS.z += p.z * a; aS.w += p.w * a;
                }
            }
        }
        for (int it = 32; it < ds; it++) {
            int e = g_lists[n * CAP + it];
            float a = comp4(ex4[e], h);
            int nbr = eidx[EE + e];
            float4 p = pr4[nbr * 32 + lane];
            aS.x += p.x * a; aS.y += p.y * a; aS.z += p.z * a; aS.w += p.w * a;
        }
    }

    float4* row = (float4*)(out + (size_t)n * 256);
    float4 v1 = row[lane];
    float4 v2 = row[32 + lane];
    v1.x += aS.x * rS; v1.y += aS.y * rS; v1.z += aS.z * rS; v1.w += aS.w * rS;
    v2.x += aT.x * rT; v2.y += aT.y * rT; v2.z += aT.z * rT; v2.w += aT.w * rT;

    float s = v1.x + v1.y + v1.z + v1.w + v2.x + v2.y + v2.z + v2.w;
    #pragma unroll
    for (int off = 16; off; off >>= 1) s += __shfl_xor_sync(0xffffffffu, s, off);
    float mu = s * (1.f / 256.f);
    float dx, sq = 0.f;
    dx = v1.x - mu; sq += dx * dx;  dx = v1.y - mu; sq += dx * dx;
    dx = v1.z - mu; sq += dx * dx;  dx = v1.w - mu; sq += dx * dx;
    dx = v2.x - mu; sq += dx * dx;  dx = v2.y - mu; sq += dx * dx;
    dx = v2.z - mu; sq += dx * dx;  dx = v2.w - mu; sq += dx * dx;
    #pragma unroll
    for (int off = 16; off; off >>= 1) sq += __shfl_xor_sync(0xffffffffu, sq, off);
    float inv = rsqrtf(sq * (1.f / 256.f) + 1e-5f);
    float4 g1 = ((const float4*)gamma)[lane], g2 = ((const float4*)gamma)[32 + lane];
    float4 b1 = ((const float4*)beta)[lane],  b2 = ((const float4*)beta)[32 + lane];
    v1.x = (v1.x - mu) * inv * g1.x + b1.x;  v1.y = (v1.y - mu) * inv * g1.y + b1.y;
    v1.z = (v1.z - mu) * inv * g1.z + b1.z;  v1.w = (v1.w - mu) * inv * g1.w + b1.w;
    v2.x = (v2.x - mu) * inv * g2.x + b2.x;  v2.y = (v2.y - mu) * inv * g2.y + b2.y;
    v2.z = (v2.z - mu) * inv * g2.z + b2.z;  v2.w = (v2.w - mu) * inv * g2.w + b2.w;
    row[lane] = v1;
    row[32 + lane] = v2;
}

// ---------------- launch ---------------------------------------------------
extern "C" void kernel_launch(void* const* d_in, const int* in_sizes, int n_in,
                              void* d_out, int out_size) {
    int o = (in_sizes[5] == 1) ? 0 : -1;
    const float* x     = (const float*)d_in[0];
    const int*   eidx  = (const int*)  d_in[1];
    const float* edges = (const float*)d_in[2];
    const float* ins   = (const float*)d_in[3];
    const int*   bids  = (const int*)  d_in[4];
    const float* Wp    = (const float*)d_in[6 + o];
    const float* We    = (const float*)d_in[7 + o];
    const float* Wsi   = (const float*)d_in[8 + o];
    const float* bsi   = (const float*)d_in[9 + o];
    const float* Wti   = (const float*)d_in[10 + o];
    const float* bti   = (const float*)d_in[11 + o];
    const float* Wei   = (const float*)d_in[12 + o];
    const float* bei   = (const float*)d_in[13 + o];
    const float* asrc  = (const float*)d_in[14 + o];
    const float* atrg  = (const float*)d_in[15 + o];
    const float* aedge = (const float*)d_in[16 + o];
    const float* bias  = (const float*)d_in[17 + o];
    const float* Wsk   = (const float*)d_in[18 + o];
    const float* gam   = (const float*)d_in[19 + o];
    const float* bet   = (const float*)d_in[20 + o];
    float* out = (float*)d_out;

    cudaFuncSetAttribute(node_kernel, cudaFuncAttributeMaxDynamicSharedMemorySize, SMEM_BYTES);
    cudaFuncSetAttribute(escore_kernel, cudaFuncAttributeMaxDynamicSharedMemorySize, ESC_SMEM);
    cudaFuncSetAttribute(scan_kernel, cudaFuncAttributeMaxDynamicSharedMemorySize, 0);

    zero_kernel<<<(NN + 255) / 256, 256>>>();
    count_kernel<<<NBLK, 256>>>(bids);
    scan_kernel<<<1, 256>>>();
    scatter_kernel<<<NBLK, 256>>>(bids);
    prep_kernel<<<BB, 128>>>(ins, Wsi, bsi, Wti, bti, Wei, bei, asrc, atrg, aedge, We);
    node_kernel<<<NN / TILE_N, 256, SMEM_BYTES>>>(x, Wp, Wsk, bias, out);
    escore_kernel<<<444, 256, ESC_SMEM>>>(eidx, edges);
    fill_kernel<<<(EE + 255) / 256, 256>>>(eidx);
    gather_kernel<<<NN / 8, 256>>>(eidx, gam, bet, out);
}

// round 7
// speedup vs baseline: 1.2296x; 1.2296x over previous
#include <cuda_runtime.h>

#define HH   4
#define FF   32
#define HFD  128          // H*F
#define FIN  128
#define EDIM 64
#define HID  256
#define BB   64
#define MLE  1500
#define NN   (BB*MLE)     // 96000
#define EE   600000
#define CAP  64           // per-node incidence capacity (P(overflow) ~ 1e-50)

typedef unsigned long long u64;

// ---------------- scratch (device globals; no allocation allowed) ----------
__device__ float g_proj[NN*HFD];      // 49.2 MB
__device__ float g_ss[NN*HH];
__device__ float g_st[NN*HH];
__device__ float g_s[EE*HH];          // scores, then exp(scores - M) in place
__device__ float g_dt[NN*HH];         // softmax denominators (trg branch)
__device__ float g_ds[NN*HH];         // softmax denominators (src branch)
__device__ float g_usrc[BB*HFD];
__device__ float g_utrg[BB*HFD];
__device__ float g_v[BB*HH*EDIM];
__device__ unsigned g_max_ord;
__device__ int g_degt[NN];
__device__ int g_degs[NN];
__device__ int g_listt[NN*CAP];       // edge ids whose trg == n
__device__ int g_lists[NN*CAP];       // edge ids whose src == n

// ---------------- helpers --------------------------------------------------
__device__ __forceinline__ unsigned f2ord(float f) {
    unsigned b = __float_as_uint(f);
    return (b & 0x80000000u) ? ~b : (b | 0x80000000u);
}
__device__ __forceinline__ float ord2f(unsigned u) {
    unsigned b = (u & 0x80000000u) ? (u & 0x7fffffffu) : ~u;
    return __uint_as_float(b);
}
__device__ __forceinline__ void red4(float* addr, float4 v) {
    asm volatile("red.global.add.v4.f32 [%0], {%1,%2,%3,%4};"
                 :: "l"(addr), "f"(v.x), "f"(v.y), "f"(v.z), "f"(v.w) : "memory");
}
__device__ __forceinline__ float lrelu(float x) { return x > 0.f ? x : 0.2f * x; }
__device__ __forceinline__ float comp4(float4 v, int h) {
    return h == 0 ? v.x : h == 1 ? v.y : h == 2 ? v.z : v.w;
}
// packed f32x2 (sm_103a FFMA2 — only reachable via PTX)
__device__ __forceinline__ u64 pack2(float lo, float hi) {
    u64 r; asm("mov.b64 %0, {%1, %2};" : "=l"(r) : "f"(lo), "f"(hi)); return r;
}
__device__ __forceinline__ void unpack2(u64 v, float& lo, float& hi) {
    asm("mov.b64 {%0, %1}, %2;" : "=f"(lo), "=f"(hi) : "l"(v));
}
__device__ __forceinline__ u64 fma2(u64 a, u64 b, u64 c) {
    u64 d; asm("fma.rn.f32x2 %0, %1, %2, %3;" : "=l"(d) : "l"(a), "l"(b), "l"(c)); return d;
}

// ---------------- K0: zero counters/denoms + init max ----------------------
__global__ void zero_kernel() {
    int i = blockIdx.x * 256 + threadIdx.x;
    if (i < NN) {
        g_degt[i] = 0; g_degs[i] = 0;
        ((float4*)g_dt)[i] = make_float4(0.f, 0.f, 0.f, 0.f);
        ((float4*)g_ds)[i] = make_float4(0.f, 0.f, 0.f, 0.f);
    }
    if (i == 0) g_max_ord = 0x007FFFFFu;   // encodes -inf
}

// ---------------- K1: per-batch instruction bridges ------------------------
__global__ void prep_kernel(const float* __restrict__ ins,
                            const float* __restrict__ Wsi, const float* __restrict__ bsi,
                            const float* __restrict__ Wti, const float* __restrict__ bti,
                            const float* __restrict__ Wei, const float* __restrict__ bei,
                            const float* __restrict__ asrc, const float* __restrict__ atrg,
                            const float* __restrict__ aedge, const float* __restrict__ Wedge) {
    __shared__ float si[HID];
    __shared__ float ce[HFD];
    int b = blockIdx.x, t = threadIdx.x;   // 128 threads
    for (int k = t; k < HID; k += 128) si[k] = ins[b * HID + k];
    __syncthreads();
    float s1 = bsi[t], s2 = bti[t], s3 = bei[t];
    for (int k = 0; k < HID; k++) {
        float iv = si[k];
        s1 += iv * Wsi[k * HFD + t];
        s2 += iv * Wti[k * HFD + t];
        s3 += iv * Wei[k * HFD + t];
    }
    g_usrc[b * HFD + t] = s1 * asrc[t];
    g_utrg[b * HFD + t] = s2 * atrg[t];
    ce[t] = s3 * aedge[t];
    __syncthreads();
    for (int o = t; o < HH * EDIM; o += 128) {
        int h = o >> 6, d = o & 63;
        float v = 0.f;
        #pragma unroll
        for (int f = 0; f < FF; f++) v += Wedge[d * HFD + h * FF + f] * ce[h * FF + f];
        g_v[b * HH * EDIM + o] = v;
    }
}

// ---------------- K2: fused node GEMM (FFMA2) + scores + skip init ---------
// sX padded to 132 floats/row so x loads are one aligned LDS.128 per 4 k.
#define TILE_N 64
#define KCOLS  256
#define XPAD   132
#define SMEM_BYTES ((FIN*KCOLS + TILE_N*XPAD) * 4)

__global__ void node_kernel(const float* __restrict__ x,
                            const float* __restrict__ Wp,
                            const float* __restrict__ Wsk,
                            const float* __restrict__ bias,
                            float* __restrict__ out) {
    extern __shared__ float smem[];
    float* sW = smem;                 // [128][256]
    float* sX = smem + FIN * KCOLS;   // [64][132] padded (reused as proj tile)
    int tid = threadIdx.x;

    const float4* Wp4 = (const float4*)Wp;
    const float4* Ws4 = (const float4*)Wsk;
    for (int i4 = tid; i4 < FIN * KCOLS / 4; i4 += 256) {
        int k = i4 >> 6, c4 = i4 & 63;
        float4 v = (c4 < 32) ? Wp4[k * 32 + c4] : Ws4[k * 32 + (c4 - 32)];
        ((float4*)sW)[i4] = v;
    }
    int base = blockIdx.x * TILE_N;
    const float4* x4 = (const float4*)x;
    for (int i = tid; i < TILE_N * 32; i += 256) {
        int r = i >> 5, k4 = i & 31;
        float4 v = x4[(base + r) * 32 + k4];
        *(float4*)&sX[r * XPAD + k4 * 4] = v;   // 528B row stride -> 16B aligned
    }
    __syncthreads();

    int tcol = tid & 31, trow = tid >> 5;
    u64 acc2[8][4];
    #pragma unroll
    for (int j = 0; j < 8; j++)
        #pragma unroll
        for (int i = 0; i < 4; i++) acc2[j][i] = 0ull;

    for (int kk = 0; kk < FIN; kk += 4) {
        float4 xv4[8];
        #pragma unroll
        for (int j = 0; j < 8; j++)
            xv4[j] = *(const float4*)&sX[(trow * 8 + j) * XPAD + kk];  // broadcast
        #pragma unroll
        for (int q = 0; q < 4; q++) {
            int k = kk + q;
            u64 wr2[4];
            #pragma unroll
            for (int i = 0; i < 4; i++)
                wr2[i] = *(const u64*)&sW[k * KCOLS + 2 * (tcol + 32 * i)];
            #pragma unroll
            for (int j = 0; j < 8; j++) {
                float xv = (q == 0) ? xv4[j].x : (q == 1) ? xv4[j].y
                          : (q == 2) ? xv4[j].z : xv4[j].w;
                u64 x2 = pack2(xv, xv);
                #pragma unroll
                for (int i = 0; i < 4; i++) acc2[j][i] = fma2(x2, wr2[i], acc2[j][i]);
            }
        }
    }
    __syncthreads();

    #pragma unroll
    for (int j = 0; j < 8; j++) {
        int ln = trow * 8 + j;
        int gn = base + ln;
        #pragma unroll
        for (int i = 0; i < 4; i++) {
            int c0 = 2 * (tcol + 32 * i);
            float lo, hi; unpack2(acc2[j][i], lo, hi);
            if (i < 2) {
                *(float2*)&g_proj[gn * HFD + c0] = make_float2(lo, hi);
                sX[ln * XPAD + c0] = lo;
                sX[ln * XPAD + c0 + 1] = hi;
            } else {
                int oj = c0 - HFD;
                float o0 = lo + bias[oj];
                float o1 = hi + bias[oj + 1];
                out[(size_t)gn * 256 + oj] = o0;
                out[(size_t)gn * 256 + oj + 1] = o1;
                out[(size_t)gn * 256 + 128 + oj] = o0;
                out[(size_t)gn * 256 + 128 + oj + 1] = o1;
            }
        }
    }
    __syncthreads();

    int ln = tid & 63, h = tid >> 6;
    int gn = base + ln;
    int b = gn / MLE;
    const float* us = g_usrc + b * HFD + h * FF;
    const float* ut = g_utrg + b * HFD + h * FF;
    const float* pr = sX + ln * XPAD + h * FF;
    float a = 0.f, c2 = 0.f;
    #pragma unroll
    for (int f = 0; f < FF; f++) { float p = pr[f]; a = fmaf(p, us[f], a); c2 = fmaf(p, ut[f], c2); }
    g_ss[gn * HH + h] = a;
    g_st[gn * HH + h] = c2;
}

// ---------------- K3: per-edge scores, v staged in SMEM --------------------
#define SV_F4 (BB*65)
#define ESC_SMEM (SV_F4*16)

__global__ void escore_kernel(const int* __restrict__ eidx,
                              const float* __restrict__ edges,
                              const int* __restrict__ bids) {
    extern __shared__ float4 sv[];
    const float4* v4 = (const float4*)g_v;
    for (int i = threadIdx.x; i < BB * 64; i += 256) {
        int b = i >> 6, r = i & 63;
        sv[b * 65 + r] = v4[i];
    }
    __syncthreads();

    float m = -3.4e38f;
    for (int e = blockIdx.x * 256 + threadIdx.x; e < EE; e += gridDim.x * 256) {
        int b = bids[e];
        int src = eidx[e], trg = eidx[EE + e];
        const float4* er = (const float4*)edges + e * 16;
        const float4* vb = sv + b * 65;
        float se0 = 0.f, se1 = 0.f, se2 = 0.f, se3 = 0.f;
        #pragma unroll
        for (int q = 0; q < 16; q++) {
            float4 ev = er[q];
            float4 v0 = vb[q], v1 = vb[16 + q], v2 = vb[32 + q], v3 = vb[48 + q];
            se0 += ev.x * v0.x + ev.y * v0.y + ev.z * v0.z + ev.w * v0.w;
            se1 += ev.x * v1.x + ev.y * v1.y + ev.z * v1.z + ev.w * v1.w;
            se2 += ev.x * v2.x + ev.y * v2.y + ev.z * v2.z + ev.w * v2.w;
            se3 += ev.x * v3.x + ev.y * v3.y + ev.z * v3.z + ev.w * v3.w;
        }
        float4 ss = ((const float4*)g_ss)[src];
        float4 st = ((const float4*)g_st)[trg];
        float s0 = lrelu(ss.x + st.x + se0);
        float s1 = lrelu(ss.y + st.y + se1);
        float s2 = lrelu(ss.z + st.z + se2);
        float s3 = lrelu(ss.w + st.w + se3);
        ((float4*)g_s)[e] = make_float4(s0, s1, s2, s3);
        m = fmaxf(m, fmaxf(fmaxf(s0, s1), fmaxf(s2, s3)));
    }
    #pragma unroll
    for (int off = 16; off; off >>= 1) m = fmaxf(m, __shfl_xor_sync(0xffffffffu, m, off));
    __shared__ float wm[8];
    if ((threadIdx.x & 31) == 0) wm[threadIdx.x >> 5] = m;
    __syncthreads();
    if (threadIdx.x < 8) {
        m = wm[threadIdx.x];
        #pragma unroll
        for (int off = 4; off; off >>= 1) m = fmaxf(m, __shfl_xor_sync(0xffu, m, off));
        if (threadIdx.x == 0) atomicMax(&g_max_ord, f2ord(m));
    }
}

// ---------------- K4: exp + incidence lists + denominators -----------------
__global__ void fill_kernel(const int* __restrict__ eidx) {
    int e = blockIdx.x * 256 + threadIdx.x;
    if (e >= EE) return;
    float M = ord2f(g_max_ord);
    float4 s = ((const float4*)g_s)[e];
    float4 ex = make_float4(__expf(s.x - M), __expf(s.y - M),
                            __expf(s.z - M), __expf(s.w - M));
    ((float4*)g_s)[e] = ex;
    int src = eidx[e], trg = eidx[EE + e];
    int pt = atomicAdd(&g_degt[trg], 1);
    if (pt < CAP) g_listt[trg * CAP + pt] = e;
    int ps = atomicAdd(&g_degs[src], 1);
    if (ps < CAP) g_lists[src * CAP + ps] = e;
    red4(g_dt + trg * 4, ex);
    red4(g_ds + src * 4, ex);
}

// ---------------- K5: gather aggregation + skip + LayerNorm ----------------
// warp per node. Entries staged in per-warp SMEM; both branches interleaved
// in one 4-unrolled loop -> up to 8 proj-row loads in flight.
__global__ void gather_kernel(const int* __restrict__ eidx,
                              const float* __restrict__ gamma,
                              const float* __restrict__ beta,
                              float* __restrict__ out) {
    __shared__ int   s_nbr[2][8][32];
    __shared__ float s_ex [2][8][32][4];
    int w = threadIdx.x >> 5;
    int n = blockIdx.x * 8 + w;
    int lane = threadIdx.x & 31;
    int h = lane >> 3;
    int dt = g_degt[n]; if (dt > CAP) dt = CAP;
    int ds = g_degs[n]; if (ds > CAP) ds = CAP;
    int m32t = dt < 32 ? dt : 32;
    int m32s = ds < 32 ? ds : 32;
    const float4* ex4 = (const float4*)g_s;
    const float4* pr4 = (const float4*)g_proj;

    if (lane < m32t) {
        int e = g_listt[n * CAP + lane];
        s_nbr[0][w][lane] = __ldg(eidx + e);
        *(float4*)&s_ex[0][w][lane][0] = __ldg(ex4 + e);
    }
    if (lane < m32s) {
        int e = g_lists[n * CAP + lane];
        s_nbr[1][w][lane] = __ldg(eidx + EE + e);
        *(float4*)&s_ex[1][w][lane][0] = __ldg(ex4 + e);
    }
    __syncwarp();

    float rT = 1.f / (comp4(((const float4*)g_dt)[n], h) + 1e-16f);
    float rS = 1.f / (comp4(((const float4*)g_ds)[n], h) + 1e-16f);

    float4 aT = make_float4(0.f, 0.f, 0.f, 0.f);
    float4 aS = make_float4(0.f, 0.f, 0.f, 0.f);
    int mmax = m32t > m32s ? m32t : m32s;
    for (int it = 0; it < mmax; it += 4) {
        #pragma unroll
        for (int j = 0; j < 4; j++) {
            int idx = it + j;
            if (idx < m32t) {
                int nbr = s_nbr[0][w][idx];           // broadcast LDS
                float a = s_ex[0][w][idx][h];         // 4-way broadcast LDS
                float4 p = __ldg(pr4 + nbr * 32 + lane);
                aT.x += p.x * a; aT.y += p.y * a; aT.z += p.z * a; aT.w += p.w * a;
            }
            if (idx < m32s) {
                int nbr = s_nbr[1][w][idx];
                float a = s_ex[1][w][idx][h];
                float4 p = __ldg(pr4 + nbr * 32 + lane);
                aS.x += p.x * a; aS.y += p.y * a; aS.z += p.z * a; aS.w += p.w * a;
            }
        }
    }
    // rare tails (deg > 32)
    for (int it = 32; it < dt; it++) {
        int e = g_listt[n * CAP + it];
        float a = comp4(ex4[e], h);
        int nbr = eidx[e];
        float4 p = pr4[nbr * 32 + lane];
        aT.x += p.x * a; aT.y += p.y * a; aT.z += p.z * a; aT.w += p.w * a;
    }
    for (int it = 32; it < ds; it++) {
        int e = g_lists[n * CAP + it];
        float a = comp4(ex4[e], h);
        int nbr = eidx[EE + e];
        float4 p = pr4[nbr * 32 + lane];
        aS.x += p.x * a; aS.y += p.y * a; aS.z += p.z * a; aS.w += p.w * a;
    }

    float4* row = (float4*)(out + (size_t)n * 256);
    float4 v1 = row[lane];        // skip+bias (src half)
    float4 v2 = row[32 + lane];   // skip+bias (trg half)
    v1.x += aS.x * rS; v1.y += aS.y * rS; v1.z += aS.z * rS; v1.w += aS.w * rS;
    v2.x += aT.x * rT; v2.y += aT.y * rT; v2.z += aT.z * rT; v2.w += aT.w * rT;

    // LayerNorm over 256 within the warp
    float s = v1.x + v1.y + v1.z + v1.w + v2.x + v2.y + v2.z + v2.w;
    #pragma unroll
    for (int off = 16; off; off >>= 1) s += __shfl_xor_sync(0xffffffffu, s, off);
    float mu = s * (1.f / 256.f);
    float dx, sq = 0.f;
    dx = v1.x - mu; sq += dx * dx;  dx = v1.y - mu; sq += dx * dx;
    dx = v1.z - mu; sq += dx * dx;  dx = v1.w - mu; sq += dx * dx;
    dx = v2.x - mu; sq += dx * dx;  dx = v2.y - mu; sq += dx * dx;
    dx = v2.z - mu; sq += dx * dx;  dx = v2.w - mu; sq += dx * dx;
    #pragma unroll
    for (int off = 16; off; off >>= 1) sq += __shfl_xor_sync(0xffffffffu, sq, off);
    float inv = rsqrtf(sq * (1.f / 256.f) + 1e-5f);
    float4 g1 = ((const float4*)gamma)[lane], g2 = ((const float4*)gamma)[32 + lane];
    float4 b1 = ((const float4*)beta)[lane],  b2 = ((const float4*)beta)[32 + lane];
    v1.x = (v1.x - mu) * inv * g1.x + b1.x;  v1.y = (v1.y - mu) * inv * g1.y + b1.y;
    v1.z = (v1.z - mu) * inv * g1.z + b1.z;  v1.w = (v1.w - mu) * inv * g1.w + b1.w;
    v2.x = (v2.x - mu) * inv * g2.x + b2.x;  v2.y = (v2.y - mu) * inv * g2.y + b2.y;
    v2.z = (v2.z - mu) * inv * g2.z + b2.z;  v2.w = (v2.w - mu) * inv * g2.w + b2.w;
    row[lane] = v1;
    row[32 + lane] = v2;
}

// ---------------- launch ---------------------------------------------------
extern "C" void kernel_launch(void* const* d_in, const int* in_sizes, int n_in,
                              void* d_out, int out_size) {
    int o = (in_sizes[5] == 1) ? 0 : -1;
    const float* x     = (const float*)d_in[0];
    const int*   eidx  = (const int*)  d_in[1];
    const float* edges = (const float*)d_in[2];
    const float* ins   = (const float*)d_in[3];
    const int*   bids  = (const int*)  d_in[4];
    const float* Wp    = (const float*)d_in[6 + o];
    const float* We    = (const float*)d_in[7 + o];
    const float* Wsi   = (const float*)d_in[8 + o];
    const float* bsi   = (const float*)d_in[9 + o];
    const float* Wti   = (const float*)d_in[10 + o];
    const float* bti   = (const float*)d_in[11 + o];
    const float* Wei   = (const float*)d_in[12 + o];
    const float* bei   = (const float*)d_in[13 + o];
    const float* asrc  = (const float*)d_in[14 + o];
    const float* atrg  = (const float*)d_in[15 + o];
    const float* aedge = (const float*)d_in[16 + o];
    const float* bias  = (const float*)d_in[17 + o];
    const float* Wsk   = (const float*)d_in[18 + o];
    const float* gam   = (const float*)d_in[19 + o];
    const float* bet   = (const float*)d_in[20 + o];
    float* out = (float*)d_out;

    cudaFuncSetAttribute(node_kernel, cudaFuncAttributeMaxDynamicSharedMemorySize, SMEM_BYTES);
    cudaFuncSetAttribute(escore_kernel, cudaFuncAttributeMaxDynamicSharedMemorySize, ESC_SMEM);

    zero_kernel<<<(NN + 255) / 256, 256>>>();
    prep_kernel<<<BB, 128>>>(ins, Wsi, bsi, Wti, bti, Wei, bei, asrc, atrg, aedge, We);
    node_kernel<<<NN / TILE_N, 256, SMEM_BYTES>>>(x, Wp, Wsk, bias, out);
    escore_kernel<<<444, 256, ESC_SMEM>>>(eidx, edges, bids);
    fill_kernel<<<(EE + 255) / 256, 256>>>(eidx);
    gather_kernel<<<NN / 8, 256>>>(eidx, gam, bet, out);
}